// round 1
// baseline (speedup 1.0000x reference)
#include <cuda_runtime.h>
#include <cstdint>

#define NB    2
#define DIM   256
#define RES   256
#define HALF  128
#define FWS   8
#define HEADS 8
#define HD    32
#define NPX   64        // FWS*FWS
#define NWIN  512       // NB * 16 * 16
#define SCALE 0.17677669529663687f

// ---- scratch (device globals; no allocation) ----
__device__ float g_ll   [NWIN * DIM * NPX];
__device__ float g_lh   [NWIN * DIM * NPX];
__device__ float g_hl   [NWIN * DIM * NPX];
__device__ float g_hh   [NWIN * DIM * NPX];
__device__ float g_llout[NWIN * DIM * NPX];

// ---- smem strides (padded for bank-conflict-free + 8B-aligned f32x2 loads) ----
#define SATT_STRIDE 66   // attn rows
#define SOUT_STRIDE 68   // out rows (16B-aligned vector reads)
#define VS_STRIDE   66
#define QS_STRIDE   34
#define KS_STRIDE   34
#define LH_STRIDE   66

#define SATT_FLOATS (HEADS * NPX * SATT_STRIDE)          // 33792
#define SOUT_FLOATS (DIM * SOUT_STRIDE)                  // 17408
#define SU_FLOATS   (HD * LH_STRIDE + 2 * NPX * QS_STRIDE) // 2112 + 4352 = 6464
#define SMEM_FLOATS (SATT_FLOATS + SOUT_FLOATS + SU_FLOATS)
#define SMEM_BYTES  (SMEM_FLOATS * 4)                    // 230,656 B <= 232,448

static_assert(SMEM_BYTES <= 232448, "smem over budget");

__device__ __forceinline__ void ffma2(uint64_t& acc, uint64_t a, uint64_t b) {
    asm("fma.rn.f32x2 %0, %1, %2, %0;" : "+l"(acc) : "l"(a), "l"(b));
}
__device__ __forceinline__ float hsum2(uint64_t v) {
    float lo, hi;
    asm("mov.b64 {%0,%1}, %2;" : "=f"(lo), "=f"(hi) : "l"(v));
    return lo + hi;
}
__device__ __forceinline__ uint64_t dup2(float w) {
    uint64_t r;
    asm("mov.b64 %0, {%1,%1};" : "=l"(r) : "f"(w));
    return r;
}

// ============================================================
// K1: forward wavelet (stride-2 2x2 depthwise, 4 subbands) -> windowed layout
// ============================================================
__global__ void k_fwt(const float* __restrict__ x, const float* __restrict__ wt) {
    int tid = blockIdx.x * blockDim.x + threadIdx.x;   // over NWIN*DIM*NPX
    int px  = tid & 63;
    int ch  = (tid >> 6) & 255;
    int win = tid >> 14;
    int b   = win >> 8;
    int wy  = (win >> 4) & 15;
    int wx  = win & 15;
    int r = px >> 3, c = px & 7;
    int Y = (wy * 8 + r) * 2;
    int X = (wx * 8 + c) * 2;
    const float* xb = x + (((size_t)(b * DIM + ch) * RES + Y) * RES + X);
    float2 a0 = *(const float2*)xb;
    float2 a1 = *(const float2*)(xb + RES);
    const float* w = wt + ch * 16;   // [s][dy][dx]
    float vll = a0.x*w[0]  + a0.y*w[1]  + a1.x*w[2]  + a1.y*w[3];
    float vlh = a0.x*w[4]  + a0.y*w[5]  + a1.x*w[6]  + a1.y*w[7];
    float vhl = a0.x*w[8]  + a0.y*w[9]  + a1.x*w[10] + a1.y*w[11];
    float vhh = a0.x*w[12] + a0.y*w[13] + a1.x*w[14] + a1.y*w[15];
    g_ll[tid] = vll; g_lh[tid] = vlh; g_hl[tid] = vhl; g_hh[tid] = vhh;
}

// ============================================================
// K2: per-window attention (one block per window) + projection
// ============================================================
__global__ void __launch_bounds__(256, 1) k_attn(
    const float* __restrict__ dww, const float* __restrict__ dwb,
    const float* __restrict__ pw,  const float* __restrict__ pb,
    const float* __restrict__ ab,  const int* __restrict__ bidx)
{
    extern __shared__ float sm[];
    float* s_attn = sm;                                  // [8][64][66]
    float* s_out  = sm + SATT_FLOATS;                    // [256][68]
    float* s_lh   = s_out + SOUT_FLOATS;                 // [32][66]  (Phase A) / s_v (Phase B)
    float* s_q    = s_lh + HD * LH_STRIDE;               // [64][34]
    float* s_k    = s_q + NPX * QS_STRIDE;               // [64][34]
    float* s_v    = s_lh;

    const int t = threadIdx.x;
    const int win = blockIdx.x;
    const size_t wbase = (size_t)win * DIM * NPX;

    // ================= Phase A: all heads' attention matrices =================
    for (int h = 0; h < HEADS; h++) {
        // load lh slice [32][64] and hl slice transposed into k_s[m][d]
        {
            const float* src  = g_lh + wbase + h * HD * NPX;
            const float* ksrc = g_hl + wbase + h * HD * NPX;
            #pragma unroll
            for (int i = 0; i < 8; i++) {
                int idx = t + 256 * i;
                int d = idx >> 6, m = idx & 63;
                s_lh[d * LH_STRIDE + m] = src[idx];
                s_k [m * KS_STRIDE + d] = ksrc[idx];
            }
        }
        __syncthreads();

        // q = depthwise 5x5 conv (pad 2, zeros outside window) + bias
        {
            int d = t >> 3, r = t & 7;
            const float* wq = dww + (h * HD + d) * 25;
            float wreg[25];
            #pragma unroll
            for (int i = 0; i < 25; i++) wreg[i] = wq[i];
            float bq = dwb[h * HD + d];
            const float* lr = s_lh + d * LH_STRIDE;
            #pragma unroll
            for (int c = 0; c < 8; c++) {
                float acc = bq;
                #pragma unroll
                for (int u = 0; u < 5; u++) {
                    int rr = r + u - 2;
                    if (rr < 0 || rr > 7) continue;
                    #pragma unroll
                    for (int v = 0; v < 5; v++) {
                        int cc = c + v - 2;
                        if (cc < 0 || cc > 7) continue;
                        acc += lr[rr * 8 + cc] * wreg[u * 5 + v];
                    }
                }
                s_q[(r * 8 + c) * QS_STRIDE + d] = acc;
            }
        }
        __syncthreads();

        // logits + softmax: thread -> row n = t>>2, m-segment (t&3)*16
        {
            int n = t >> 2, mseg = (t & 3) * 16;
            uint64_t q2[16];
            const float* qrow = s_q + n * QS_STRIDE;
            #pragma unroll
            for (int i = 0; i < 16; i++) q2[i] = *(const uint64_t*)(qrow + 2 * i);
            const int* brow = bidx + n * 64 + mseg;
            const float* abh = ab + h * 64;
            float logits[16];
            #pragma unroll
            for (int mm = 0; mm < 16; mm++) {
                const float* krow = s_k + (mseg + mm) * KS_STRIDE;
                uint64_t acc = 0ull;
                #pragma unroll
                for (int i = 0; i < 16; i++) {
                    uint64_t k2 = *(const uint64_t*)(krow + 2 * i);
                    ffma2(acc, q2[i], k2);
                }
                logits[mm] = hsum2(acc) * SCALE + abh[brow[mm]];
            }
            float mx = logits[0];
            #pragma unroll
            for (int i = 1; i < 16; i++) mx = fmaxf(mx, logits[i]);
            mx = fmaxf(mx, __shfl_xor_sync(0xffffffffu, mx, 1));
            mx = fmaxf(mx, __shfl_xor_sync(0xffffffffu, mx, 2));
            float sum = 0.f;
            #pragma unroll
            for (int i = 0; i < 16; i++) { logits[i] = __expf(logits[i] - mx); sum += logits[i]; }
            sum += __shfl_xor_sync(0xffffffffu, sum, 1);
            sum += __shfl_xor_sync(0xffffffffu, sum, 2);
            float inv = 1.0f / sum;
            float* arow = s_attn + (h * 64 + n) * SATT_STRIDE + mseg;
            #pragma unroll
            for (int i = 0; i < 16; i++) arow[i] = logits[i] * inv;
        }
        __syncthreads();
    }

    // ================= Phase B: sequential head recurrence (V path) =================
    {
        const float* src = g_ll + wbase;   // head 0 slice
        #pragma unroll
        for (int i = 0; i < 8; i++) {
            int idx = t + 256 * i;
            int d = idx >> 6, m = idx & 63;
            s_v[d * VS_STRIDE + m] = src[idx];
        }
    }
    __syncthreads();

    {
        const int d = t >> 3, j = t & 7;   // thread owns (d, n = 8i + j)
        for (int h = 0; h < HEADS; h++) {
            if (h > 0) {
                const float* src = g_ll + wbase + h * HD * NPX;
                #pragma unroll
                for (int i = 0; i < 8; i++) {
                    int idx = t + 256 * i;
                    int dd = idx >> 6, m = idx & 63;
                    s_v[dd * VS_STRIDE + m] += src[idx];
                }
                __syncthreads();
            }
            uint64_t acc2[8];
            #pragma unroll
            for (int i = 0; i < 8; i++) acc2[i] = 0ull;
            const float* vrow = s_v + d * VS_STRIDE;
            const float* ahb = s_attn + (h * 64 + j) * SATT_STRIDE;
            #pragma unroll 8
            for (int mp = 0; mp < 32; mp++) {
                uint64_t v2 = *(const uint64_t*)(vrow + 2 * mp);
                #pragma unroll
                for (int i = 0; i < 8; i++) {
                    uint64_t a2 = *(const uint64_t*)(ahb + (8 * i) * SATT_STRIDE + 2 * mp);
                    ffma2(acc2[i], v2, a2);
                }
            }
            __syncthreads();   // all reads of s_v done before overwrite
            #pragma unroll
            for (int i = 0; i < 8; i++) {
                float o = hsum2(acc2[i]);
                int n = 8 * i + j;
                s_out[(h * HD + d) * SOUT_STRIDE + n] = o;
                s_v[d * VS_STRIDE + n] = o;
            }
            __syncthreads();
        }
    }

    // ================= Phase C: relu + 256x256 projection + bias =================
    #pragma unroll
    for (int i = 0; i < 64; i++) {
        int idx = t + 256 * i;
        int o = idx >> 6, px = idx & 63;
        float v = s_out[o * SOUT_STRIDE + px];
        s_out[o * SOUT_STRIDE + px] = fmaxf(v, 0.f);
    }
    __syncthreads();

    {
        const int o = t;
        uint64_t acc2[32];
        #pragma unroll
        for (int i = 0; i < 32; i++) acc2[i] = 0ull;
        const float* wrow = pw + o * 256;
        for (int c4 = 0; c4 < 256; c4 += 4) {
            float4 wv = *(const float4*)(wrow + c4);
            #pragma unroll
            for (int q = 0; q < 4; q++) {
                float wq = (q == 0) ? wv.x : (q == 1) ? wv.y : (q == 2) ? wv.z : wv.w;
                uint64_t w2 = dup2(wq);
                const float* srow = s_out + (c4 + q) * SOUT_STRIDE;
                #pragma unroll
                for (int i = 0; i < 16; i++) {
                    ulonglong2 vv = *(const ulonglong2*)(srow + 4 * i);
                    ffma2(acc2[2 * i],     vv.x, w2);
                    ffma2(acc2[2 * i + 1], vv.y, w2);
                }
            }
        }
        __syncthreads();   // all reads of s_out done before overwrite
        float bias = pb[o];
        float* orow = s_out + o * SOUT_STRIDE;
        #pragma unroll
        for (int i = 0; i < 32; i++) {
            float lo, hi;
            asm("mov.b64 {%0,%1}, %2;" : "=f"(lo), "=f"(hi) : "l"(acc2[i]));
            orow[2 * i]     = lo + bias;
            orow[2 * i + 1] = hi + bias;
        }
    }
    __syncthreads();

    // coalesced store of projected LL band
    {
        float* dst = g_llout + wbase;
        #pragma unroll
        for (int i = 0; i < 64; i++) {
            int idx = t + 256 * i;
            int o = idx >> 6, px = idx & 63;
            dst[idx] = s_out[o * SOUT_STRIDE + px];
        }
    }
}

// ============================================================
// K3: inverse wavelet (lhs_dilation conv collapses to parity-indexed taps)
// ============================================================
__global__ void k_iwt(const float* __restrict__ iwt, float* __restrict__ out) {
    int tid = blockIdx.x * blockDim.x + threadIdx.x;   // over NB*DIM*RES*RES
    int X  = tid & 255;
    int Y  = (tid >> 8) & 255;
    int ch = (tid >> 16) & 255;
    int b  = tid >> 24;
    int y = Y >> 1, x = X >> 1;
    int win = (b * 16 + (y >> 3)) * 16 + (x >> 3);
    int px  = (y & 7) * 8 + (x & 7);
    int base = (win * DIM + ch) * NPX + px;
    const float* w = iwt + ch * 16 + (Y & 1) * 2 + (X & 1);
    float v = g_llout[base] * w[0] + g_lh[base] * w[4]
            + g_hl[base]   * w[8] + g_hh[base] * w[12];
    out[tid] = v;
}

// ============================================================
extern "C" void kernel_launch(void* const* d_in, const int* in_sizes, int n_in,
                              void* d_out, int out_size) {
    const float* x   = (const float*)d_in[0];
    const float* wt  = (const float*)d_in[1];
    const float* iwt = (const float*)d_in[2];
    const float* dww = (const float*)d_in[3];
    const float* dwb = (const float*)d_in[4];
    const float* pw  = (const float*)d_in[5];
    const float* pb  = (const float*)d_in[6];
    const float* ab  = (const float*)d_in[7];
    const int*   bidx= (const int*)d_in[8];
    float* out = (float*)d_out;

    (void)in_sizes; (void)n_in; (void)out_size;

    cudaFuncSetAttribute(k_attn, cudaFuncAttributeMaxDynamicSharedMemorySize, SMEM_BYTES);

    k_fwt<<<(NWIN * DIM * NPX) / 256, 256>>>(x, wt);
    k_attn<<<NWIN, 256, SMEM_BYTES>>>(dww, dwb, pw, pb, ab, bidx);
    k_iwt<<<(NB * DIM * RES * RES) / 256, 256>>>(iwt, out);
}

// round 2
// speedup vs baseline: 2.1978x; 2.1978x over previous
#include <cuda_runtime.h>
#include <cstdint>

#define NB    2
#define DIM   256
#define RES   256
#define FWS   8
#define HEADS 8
#define HD    32
#define NPX   64        // FWS*FWS
#define NWIN  512       // NB * 16 * 16
#define SCALE 0.17677669529663687f

// ---- scratch (device globals; no allocation) ----
__device__ float g_ll   [NWIN * DIM * NPX];
__device__ float g_lh   [NWIN * DIM * NPX];
__device__ float g_hl   [NWIN * DIM * NPX];
__device__ float g_hh   [NWIN * DIM * NPX];
__device__ float g_llout[NWIN * DIM * NPX];
__device__ float g_attn [NWIN * HEADS * NPX * NPX];          // [win][head][n][m]
__device__ float g_pout [DIM * NWIN * NPX];                  // [c][win*64+px], relu'd

__device__ __forceinline__ void ffma2(uint64_t& acc, uint64_t a, uint64_t b) {
    asm("fma.rn.f32x2 %0, %1, %2, %0;" : "+l"(acc) : "l"(a), "l"(b));
}
__device__ __forceinline__ float hsum2(uint64_t v) {
    float lo, hi;
    asm("mov.b64 {%0,%1}, %2;" : "=f"(lo), "=f"(hi) : "l"(v));
    return lo + hi;
}
__device__ __forceinline__ uint64_t dup2(float w) {
    uint64_t r;
    asm("mov.b64 %0, {%1,%1};" : "=l"(r) : "f"(w));
    return r;
}

// ============================================================
// K1: forward wavelet -> windowed layout. 2 horizontal px per thread (float4 loads)
// ============================================================
__global__ void k_fwt(const float* __restrict__ x, const float* __restrict__ wt) {
    int tid = blockIdx.x * blockDim.x + threadIdx.x;   // over NWIN*DIM*32
    int p   = tid & 31;            // r*4 + c2
    int ch  = (tid >> 5) & 255;
    int win = tid >> 13;
    int b   = win >> 8;
    int wy  = (win >> 4) & 15;
    int wx  = win & 15;
    int r = p >> 2, c2 = p & 3;
    int Y = (wy * 8 + r) * 2;
    int X = (wx * 8 + c2 * 2) * 2;
    const float* xb = x + (((size_t)(b * DIM + ch) * RES + Y) * RES + X);
    float4 a0 = *(const float4*)xb;
    float4 a1 = *(const float4*)(xb + RES);
    const float* w = wt + ch * 16;   // [s][dy][dx]
    int obase = (win * DIM + ch) * NPX + r * 8 + c2 * 2;
    #pragma unroll
    for (int s = 0; s < 4; s++) {
        float w0 = w[4*s], w1 = w[4*s+1], w2 = w[4*s+2], w3 = w[4*s+3];
        float v0 = a0.x*w0 + a0.y*w1 + a1.x*w2 + a1.y*w3;
        float v1 = a0.z*w0 + a0.w*w1 + a1.z*w2 + a1.w*w3;
        float2 vv = make_float2(v0, v1);
        float* dst = (s == 0) ? g_ll : (s == 1) ? g_lh : (s == 2) ? g_hl : g_hh;
        *(float2*)(dst + obase) = vv;
    }
}

// ============================================================
// K2a: attention matrices, one block per (window, head)
// ============================================================
__global__ void __launch_bounds__(256) k_attnmat(
    const float* __restrict__ dww, const float* __restrict__ dwb,
    const float* __restrict__ ab,  const int* __restrict__ bidx)
{
    __shared__ float s_lh[HD * 66];
    __shared__ float s_k [NPX * 34];
    __shared__ float s_q [NPX * 34];

    const int t = threadIdx.x;
    const int bw = blockIdx.x;
    const int win = bw >> 3, h = bw & 7;
    const size_t base = (size_t)win * DIM * NPX + h * HD * NPX;
    const float* lsrc = g_lh + base;
    const float* ksrc = g_hl + base;
    #pragma unroll
    for (int i = 0; i < 8; i++) {
        int idx = t + 256 * i;
        int d = idx >> 6, m = idx & 63;
        s_lh[d * 66 + m] = lsrc[idx];
        s_k [m * 34 + d] = ksrc[idx];
    }
    __syncthreads();

    // q = depthwise 5x5 conv (zero pad outside window) + bias
    {
        int d = t >> 3, r = t & 7;
        const float* wq = dww + (h * HD + d) * 25;
        float wreg[25];
        #pragma unroll
        for (int i = 0; i < 25; i++) wreg[i] = wq[i];
        float bq = dwb[h * HD + d];
        const float* lr = s_lh + d * 66;
        #pragma unroll
        for (int c = 0; c < 8; c++) {
            float acc = bq;
            #pragma unroll
            for (int u = 0; u < 5; u++) {
                int rr = r + u - 2;
                if (rr < 0 || rr > 7) continue;
                #pragma unroll
                for (int v = 0; v < 5; v++) {
                    int cc = c + v - 2;
                    if (cc < 0 || cc > 7) continue;
                    acc += lr[rr * 8 + cc] * wreg[u * 5 + v];
                }
            }
            s_q[(r * 8 + c) * 34 + d] = acc;
        }
    }
    __syncthreads();

    // logits + softmax: thread (n = t>>2, q = t&3), m = q + 4*mm (bank-conflict-free)
    {
        int n = t >> 2, q = t & 3;
        uint64_t q2[16];
        const float* qrow = s_q + n * 34;
        #pragma unroll
        for (int i = 0; i < 16; i++) q2[i] = *(const uint64_t*)(qrow + 2 * i);
        const int* brow = bidx + n * 64;
        const float* abh = ab + h * 64;
        float logits[16];
        #pragma unroll
        for (int mm = 0; mm < 16; mm++) {
            int m = q + 4 * mm;
            const float* krow = s_k + m * 34;
            uint64_t acc = 0ull;
            #pragma unroll
            for (int i = 0; i < 16; i++) {
                uint64_t k2 = *(const uint64_t*)(krow + 2 * i);
                ffma2(acc, q2[i], k2);
            }
            logits[mm] = hsum2(acc) * SCALE + abh[brow[m]];
        }
        float mx = logits[0];
        #pragma unroll
        for (int i = 1; i < 16; i++) mx = fmaxf(mx, logits[i]);
        mx = fmaxf(mx, __shfl_xor_sync(0xffffffffu, mx, 1));
        mx = fmaxf(mx, __shfl_xor_sync(0xffffffffu, mx, 2));
        float sum = 0.f;
        #pragma unroll
        for (int i = 0; i < 16; i++) { logits[i] = __expf(logits[i] - mx); sum += logits[i]; }
        sum += __shfl_xor_sync(0xffffffffu, sum, 1);
        sum += __shfl_xor_sync(0xffffffffu, sum, 2);
        float inv = 1.0f / sum;
        float* arow = g_attn + ((size_t)bw * 64 + n) * 64;
        #pragma unroll
        for (int mm = 0; mm < 16; mm++) arow[q + 4 * mm] = logits[mm] * inv;
    }
}

// ============================================================
// K2b: sequential head recurrence (V path), one block per window
// ============================================================
__global__ void __launch_bounds__(256) k_vrec() {
    __shared__ float s_v[HD * 66];
    __shared__ float s_a[NPX * 66];

    const int t = threadIdx.x;
    const int win = blockIdx.x;
    const size_t wbase = (size_t)win * DIM * NPX;
    const int d = t >> 3, j = t & 7;

    for (int h = 0; h < HEADS; h++) {
        __syncthreads();
        // stage attn tile for this head
        const float* asrc = g_attn + ((size_t)(win * 8 + h)) * 4096;
        #pragma unroll
        for (int i = 0; i < 16; i++) {
            int idx = t + 256 * i;
            int n = idx >> 6, m = idx & 63;
            s_a[n * 66 + m] = asrc[idx];
        }
        // v update
        const float* vsrc = g_ll + wbase + h * HD * NPX;
        #pragma unroll
        for (int i = 0; i < 8; i++) {
            int idx = t + 256 * i;
            int dd = idx >> 6, m = idx & 63;
            if (h == 0) s_v[dd * 66 + m]  = vsrc[idx];
            else        s_v[dd * 66 + m] += vsrc[idx];
        }
        __syncthreads();

        uint64_t acc2[8];
        #pragma unroll
        for (int i = 0; i < 8; i++) acc2[i] = 0ull;
        const float* vrow = s_v + d * 66;
        const float* ajb  = s_a + j * 66;
        #pragma unroll 8
        for (int mp = 0; mp < 32; mp++) {
            uint64_t v2 = *(const uint64_t*)(vrow + 2 * mp);
            #pragma unroll
            for (int i = 0; i < 8; i++) {
                uint64_t a2 = *(const uint64_t*)(ajb + (8 * i) * 66 + 2 * mp);
                ffma2(acc2[i], v2, a2);
            }
        }
        __syncthreads();   // all reads of s_v done before overwrite

        float* prow = g_pout + (size_t)(h * HD + d) * (NWIN * NPX) + win * NPX;
        #pragma unroll
        for (int i = 0; i < 8; i++) {
            float o = hsum2(acc2[i]);
            int nn = 8 * i + j;
            s_v[d * 66 + nn] = o;          // recurrence uses pre-relu
            prow[nn] = fmaxf(o, 0.f);      // projection input is relu'd
        }
    }
}

// ============================================================
// K2c: 256x256 projection over all windows (one block per window)
// ============================================================
#define SIN_STRIDE 68
#define PROJ_SMEM (DIM * SIN_STRIDE * 4)   // 69632 B

__global__ void __launch_bounds__(256) k_proj(
    const float* __restrict__ pw, const float* __restrict__ pb)
{
    extern __shared__ float s_in[];   // [256][68] input; later reused [256][65] output
    const int t = threadIdx.x;
    const int win = blockIdx.x;

    const float* src = g_pout + win * NPX;
    #pragma unroll
    for (int i = 0; i < 64; i++) {
        int idx = t + 256 * i;
        int c = idx >> 6, px = idx & 63;
        s_in[c * SIN_STRIDE + px] = src[(size_t)c * (NWIN * NPX) + px];
    }
    __syncthreads();

    const int o = t;
    uint64_t acc2[32];
    #pragma unroll
    for (int i = 0; i < 32; i++) acc2[i] = 0ull;
    const float* wrow = pw + o * 256;
    for (int c4 = 0; c4 < 256; c4 += 4) {
        float4 wv = *(const float4*)(wrow + c4);
        #pragma unroll
        for (int q = 0; q < 4; q++) {
            float wq = (q == 0) ? wv.x : (q == 1) ? wv.y : (q == 2) ? wv.z : wv.w;
            uint64_t w2 = dup2(wq);
            const float* srow = s_in + (c4 + q) * SIN_STRIDE;
            #pragma unroll
            for (int i = 0; i < 16; i++) {
                ulonglong2 vv = *(const ulonglong2*)(srow + 4 * i);
                ffma2(acc2[2 * i],     vv.x, w2);
                ffma2(acc2[2 * i + 1], vv.y, w2);
            }
        }
    }
    __syncthreads();   // all reads of s_in done before overwrite

    float bias = pb[o];
    #pragma unroll
    for (int i = 0; i < 32; i++) {
        float lo, hi;
        asm("mov.b64 {%0,%1}, %2;" : "=f"(lo), "=f"(hi) : "l"(acc2[i]));
        s_in[o * 65 + 2 * i]     = lo + bias;
        s_in[o * 65 + 2 * i + 1] = hi + bias;
    }
    __syncthreads();

    float* dst = g_llout + (size_t)win * DIM * NPX;
    #pragma unroll
    for (int i = 0; i < 64; i++) {
        int idx = t + 256 * i;
        int c = idx >> 6, px = idx & 63;
        dst[idx] = s_in[c * 65 + px];
    }
}

// ============================================================
// K3: inverse wavelet (lhs_dilation conv collapses to parity-indexed taps)
// ============================================================
__global__ void k_iwt(const float* __restrict__ iwt, float* __restrict__ out) {
    int tid = blockIdx.x * blockDim.x + threadIdx.x;   // over NB*DIM*RES*RES
    int X  = tid & 255;
    int Y  = (tid >> 8) & 255;
    int ch = (tid >> 16) & 255;
    int b  = tid >> 24;
    int y = Y >> 1, x = X >> 1;
    int win = (b * 16 + (y >> 3)) * 16 + (x >> 3);
    int px  = (y & 7) * 8 + (x & 7);
    int base = (win * DIM + ch) * NPX + px;
    const float* w = iwt + ch * 16 + (Y & 1) * 2 + (X & 1);
    float v = g_llout[base] * w[0] + g_lh[base] * w[4]
            + g_hl[base]   * w[8] + g_hh[base] * w[12];
    out[tid] = v;
}

// ============================================================
extern "C" void kernel_launch(void* const* d_in, const int* in_sizes, int n_in,
                              void* d_out, int out_size) {
    const float* x   = (const float*)d_in[0];
    const float* wt  = (const float*)d_in[1];
    const float* iwt = (const float*)d_in[2];
    const float* dww = (const float*)d_in[3];
    const float* dwb = (const float*)d_in[4];
    const float* pw  = (const float*)d_in[5];
    const float* pb  = (const float*)d_in[6];
    const float* ab  = (const float*)d_in[7];
    const int*   bidx= (const int*)d_in[8];
    float* out = (float*)d_out;

    (void)in_sizes; (void)n_in; (void)out_size;

    cudaFuncSetAttribute(k_proj, cudaFuncAttributeMaxDynamicSharedMemorySize, PROJ_SMEM);

    k_fwt    <<<(NWIN * DIM * 32) / 256, 256>>>(x, wt);
    k_attnmat<<<NWIN * HEADS, 256>>>(dww, dwb, ab, bidx);
    k_vrec   <<<NWIN, 256>>>();
    k_proj   <<<NWIN, 256, PROJ_SMEM>>>(pw, pb);
    k_iwt    <<<(NB * DIM * RES * RES) / 256, 256>>>(iwt, out);
}

// round 3
// speedup vs baseline: 2.3053x; 1.0489x over previous
#include <cuda_runtime.h>
#include <cstdint>

#define NB    2
#define DIM   256
#define RES   256
#define FWS   8
#define HEADS 8
#define HD    32
#define NPX   64        // FWS*FWS
#define NWIN  512       // NB * 16 * 16
#define SCALE 0.17677669529663687f

// ---- scratch (device globals; no allocation) ----
__device__ float g_ll   [NWIN * DIM * NPX];
__device__ float g_lh   [NWIN * DIM * NPX];
__device__ float g_hl   [NWIN * DIM * NPX];
__device__ float g_hh   [NWIN * DIM * NPX];
__device__ float g_llout[NWIN * DIM * NPX];
__device__ float g_attn [NWIN * HEADS * NPX * NPX];          // [win][head][n][m]
__device__ float g_pout [DIM * NWIN * NPX];                  // [c][win*64+px], relu'd

__device__ __forceinline__ void ffma2(uint64_t& acc, uint64_t a, uint64_t b) {
    asm("fma.rn.f32x2 %0, %1, %2, %0;" : "+l"(acc) : "l"(a), "l"(b));
}
__device__ __forceinline__ float hsum2(uint64_t v) {
    float lo, hi;
    asm("mov.b64 {%0,%1}, %2;" : "=f"(lo), "=f"(hi) : "l"(v));
    return lo + hi;
}
__device__ __forceinline__ uint64_t dup2(float w) {
    uint64_t r;
    asm("mov.b64 %0, {%1,%1};" : "=l"(r) : "f"(w));
    return r;
}
__device__ __forceinline__ float2 unp2(uint64_t v) {
    float lo, hi;
    asm("mov.b64 {%0,%1}, %2;" : "=f"(lo), "=f"(hi) : "l"(v));
    return make_float2(lo, hi);
}

// ============================================================
// K1: forward wavelet -> windowed layout. 2 horizontal px per thread (float4 loads)
// ============================================================
__global__ void k_fwt(const float* __restrict__ x, const float* __restrict__ wt) {
    int tid = blockIdx.x * blockDim.x + threadIdx.x;   // over NWIN*DIM*32
    int p   = tid & 31;            // r*4 + c2
    int ch  = (tid >> 5) & 255;
    int win = tid >> 13;
    int b   = win >> 8;
    int wy  = (win >> 4) & 15;
    int wx  = win & 15;
    int r = p >> 2, c2 = p & 3;
    int Y = (wy * 8 + r) * 2;
    int X = (wx * 8 + c2 * 2) * 2;
    const float* xb = x + (((size_t)(b * DIM + ch) * RES + Y) * RES + X);
    float4 a0 = *(const float4*)xb;
    float4 a1 = *(const float4*)(xb + RES);
    const float* w = wt + ch * 16;   // [s][dy][dx]
    int obase = (win * DIM + ch) * NPX + r * 8 + c2 * 2;
    #pragma unroll
    for (int s = 0; s < 4; s++) {
        float w0 = w[4*s], w1 = w[4*s+1], w2 = w[4*s+2], w3 = w[4*s+3];
        float v0 = a0.x*w0 + a0.y*w1 + a1.x*w2 + a1.y*w3;
        float v1 = a0.z*w0 + a0.w*w1 + a1.z*w2 + a1.w*w3;
        float2 vv = make_float2(v0, v1);
        float* dst = (s == 0) ? g_ll : (s == 1) ? g_lh : (s == 2) ? g_hl : g_hh;
        *(float2*)(dst + obase) = vv;
    }
}

// ============================================================
// K2a: attention matrices, one block per (window, head)
// ============================================================
__global__ void __launch_bounds__(256) k_attnmat(
    const float* __restrict__ dww, const float* __restrict__ dwb,
    const float* __restrict__ ab,  const int* __restrict__ bidx)
{
    __shared__ float s_lh[HD * 66];
    __shared__ float s_k [NPX * 34];
    __shared__ float s_q [NPX * 34];

    const int t = threadIdx.x;
    const int bw = blockIdx.x;
    const int win = bw >> 3, h = bw & 7;
    const size_t base = (size_t)win * DIM * NPX + h * HD * NPX;
    const float* lsrc = g_lh + base;
    const float* ksrc = g_hl + base;
    #pragma unroll
    for (int i = 0; i < 8; i++) {
        int idx = t + 256 * i;
        int d = idx >> 6, m = idx & 63;
        s_lh[d * 66 + m] = lsrc[idx];
        s_k [m * 34 + d] = ksrc[idx];
    }
    __syncthreads();

    // q = depthwise 5x5 conv (zero pad outside window) + bias
    {
        int d = t >> 3, r = t & 7;
        const float* wq = dww + (h * HD + d) * 25;
        float wreg[25];
        #pragma unroll
        for (int i = 0; i < 25; i++) wreg[i] = wq[i];
        float bq = dwb[h * HD + d];
        const float* lr = s_lh + d * 66;
        #pragma unroll
        for (int c = 0; c < 8; c++) {
            float acc = bq;
            #pragma unroll
            for (int u = 0; u < 5; u++) {
                int rr = r + u - 2;
                if (rr < 0 || rr > 7) continue;
                #pragma unroll
                for (int v = 0; v < 5; v++) {
                    int cc = c + v - 2;
                    if (cc < 0 || cc > 7) continue;
                    acc += lr[rr * 8 + cc] * wreg[u * 5 + v];
                }
            }
            s_q[(r * 8 + c) * 34 + d] = acc;
        }
    }
    __syncthreads();

    // logits + softmax: thread (n = t>>2, q = t&3), m = q + 4*mm (bank-conflict-free)
    {
        int n = t >> 2, q = t & 3;
        uint64_t q2[16];
        const float* qrow = s_q + n * 34;
        #pragma unroll
        for (int i = 0; i < 16; i++) q2[i] = *(const uint64_t*)(qrow + 2 * i);
        const int* brow = bidx + n * 64;
        const float* abh = ab + h * 64;
        float logits[16];
        #pragma unroll
        for (int mm = 0; mm < 16; mm++) {
            int m = q + 4 * mm;
            const float* krow = s_k + m * 34;
            uint64_t acc = 0ull;
            #pragma unroll
            for (int i = 0; i < 16; i++) {
                uint64_t k2 = *(const uint64_t*)(krow + 2 * i);
                ffma2(acc, q2[i], k2);
            }
            logits[mm] = hsum2(acc) * SCALE + abh[brow[m]];
        }
        float mx = logits[0];
        #pragma unroll
        for (int i = 1; i < 16; i++) mx = fmaxf(mx, logits[i]);
        mx = fmaxf(mx, __shfl_xor_sync(0xffffffffu, mx, 1));
        mx = fmaxf(mx, __shfl_xor_sync(0xffffffffu, mx, 2));
        float sum = 0.f;
        #pragma unroll
        for (int i = 0; i < 16; i++) { logits[i] = __expf(logits[i] - mx); sum += logits[i]; }
        sum += __shfl_xor_sync(0xffffffffu, sum, 1);
        sum += __shfl_xor_sync(0xffffffffu, sum, 2);
        float inv = 1.0f / sum;
        float* arow = g_attn + ((size_t)bw * 64 + n) * 64;
        #pragma unroll
        for (int mm = 0; mm < 16; mm++) arow[q + 4 * mm] = logits[mm] * inv;
    }
}

// ============================================================
// K2b: sequential head recurrence (V path), one block per window
// ============================================================
__global__ void __launch_bounds__(256) k_vrec() {
    __shared__ float s_v[HD * 66];
    __shared__ float s_a[NPX * 66];

    const int t = threadIdx.x;
    const int win = blockIdx.x;
    const size_t wbase = (size_t)win * DIM * NPX;
    const int d = t >> 3, j = t & 7;

    for (int h = 0; h < HEADS; h++) {
        __syncthreads();
        // stage attn tile for this head
        const float* asrc = g_attn + ((size_t)(win * 8 + h)) * 4096;
        #pragma unroll
        for (int i = 0; i < 16; i++) {
            int idx = t + 256 * i;
            int n = idx >> 6, m = idx & 63;
            s_a[n * 66 + m] = asrc[idx];
        }
        // v update
        const float* vsrc = g_ll + wbase + h * HD * NPX;
        #pragma unroll
        for (int i = 0; i < 8; i++) {
            int idx = t + 256 * i;
            int dd = idx >> 6, m = idx & 63;
            if (h == 0) s_v[dd * 66 + m]  = vsrc[idx];
            else        s_v[dd * 66 + m] += vsrc[idx];
        }
        __syncthreads();

        uint64_t acc2[8];
        #pragma unroll
        for (int i = 0; i < 8; i++) acc2[i] = 0ull;
        const float* vrow = s_v + d * 66;
        const float* ajb  = s_a + j * 66;
        #pragma unroll 8
        for (int mp = 0; mp < 32; mp++) {
            uint64_t v2 = *(const uint64_t*)(vrow + 2 * mp);
            #pragma unroll
            for (int i = 0; i < 8; i++) {
                uint64_t a2 = *(const uint64_t*)(ajb + (8 * i) * 66 + 2 * mp);
                ffma2(acc2[i], v2, a2);
            }
        }
        __syncthreads();   // all reads of s_v done before overwrite

        float* prow = g_pout + (size_t)(h * HD + d) * (NWIN * NPX) + win * NPX;
        #pragma unroll
        for (int i = 0; i < 8; i++) {
            float o = hsum2(acc2[i]);
            int nn = 8 * i + j;
            s_v[d * 66 + nn] = o;          // recurrence uses pre-relu
            prow[nn] = fmaxf(o, 0.f);      // projection input is relu'd
        }
    }
}

// ============================================================
// K2c: 256x256 projection. One block = (window, half of output channels).
// Thread = 2 output channels x 16 px (px = seg*4 + j + 16*i, conflict-free LDS.128)
// ============================================================
#define SIN_STRIDE 68
#define PROJ_SMEM (DIM * SIN_STRIDE * 4)   // 69632 B

__global__ void __launch_bounds__(256) k_proj(
    const float* __restrict__ pw, const float* __restrict__ pb)
{
    extern __shared__ float s_in[];   // [256][68]
    const int t = threadIdx.x;
    const int win  = blockIdx.x >> 1;
    const int half = blockIdx.x & 1;

    // stage relu'd attention output [256 ch][64 px] for this window
    const float* src = g_pout + win * NPX;
    #pragma unroll
    for (int i = 0; i < 64; i++) {
        int idx = t + 256 * i;
        int c = idx >> 6, px = idx & 63;
        s_in[c * SIN_STRIDE + px] = src[(size_t)c * (NWIN * NPX) + px];
    }
    __syncthreads();

    const int pair = t >> 2;          // 0..63 -> output-channel pair
    const int seg  = t & 3;           // px group: px = seg*4 + j + 16*i
    const int oc   = half * 128 + pair * 2;
    const float* w0p = pw + oc * 256;
    const float* w1p = w0p + 256;
    const float* sbase = s_in + seg * 4;

    uint64_t acc[2][8];
    #pragma unroll
    for (int o = 0; o < 2; o++)
        #pragma unroll
        for (int i = 0; i < 8; i++) acc[o][i] = 0ull;

    for (int c4 = 0; c4 < 256; c4 += 4) {
        float4 wv0 = *(const float4*)(w0p + c4);
        float4 wv1 = *(const float4*)(w1p + c4);
        #pragma unroll
        for (int q = 0; q < 4; q++) {
            float a = (q == 0) ? wv0.x : (q == 1) ? wv0.y : (q == 2) ? wv0.z : wv0.w;
            float b = (q == 0) ? wv1.x : (q == 1) ? wv1.y : (q == 2) ? wv1.z : wv1.w;
            uint64_t wa = dup2(a), wb = dup2(b);
            const float* srow = sbase + (c4 + q) * SIN_STRIDE;
            #pragma unroll
            for (int i = 0; i < 4; i++) {
                ulonglong2 vv = *(const ulonglong2*)(srow + 16 * i);
                ffma2(acc[0][2 * i],     vv.x, wa);
                ffma2(acc[0][2 * i + 1], vv.y, wa);
                ffma2(acc[1][2 * i],     vv.x, wb);
                ffma2(acc[1][2 * i + 1], vv.y, wb);
            }
        }
    }

    // bias + store directly to g_llout (16B-aligned float4 stores)
    float bias[2] = { pb[oc], pb[oc + 1] };
    float* wdst = g_llout + (size_t)win * DIM * NPX;
    #pragma unroll
    for (int o = 0; o < 2; o++) {
        float* dst = wdst + (oc + o) * NPX + seg * 4;
        #pragma unroll
        for (int i = 0; i < 4; i++) {
            float2 lo = unp2(acc[o][2 * i]);
            float2 hi = unp2(acc[o][2 * i + 1]);
            float4 v4 = make_float4(lo.x + bias[o], lo.y + bias[o],
                                    hi.x + bias[o], hi.y + bias[o]);
            *(float4*)(dst + 16 * i) = v4;
        }
    }
}

// ============================================================
// K3: inverse wavelet (lhs_dilation conv collapses to parity-indexed taps)
// ============================================================
__global__ void k_iwt(const float* __restrict__ iwt, float* __restrict__ out) {
    int tid = blockIdx.x * blockDim.x + threadIdx.x;   // over NB*DIM*RES*RES
    int X  = tid & 255;
    int Y  = (tid >> 8) & 255;
    int ch = (tid >> 16) & 255;
    int b  = tid >> 24;
    int y = Y >> 1, x = X >> 1;
    int win = (b * 16 + (y >> 3)) * 16 + (x >> 3);
    int px  = (y & 7) * 8 + (x & 7);
    int base = (win * DIM + ch) * NPX + px;
    const float* w = iwt + ch * 16 + (Y & 1) * 2 + (X & 1);
    float v = g_llout[base] * w[0] + g_lh[base] * w[4]
            + g_hl[base]   * w[8] + g_hh[base] * w[12];
    out[tid] = v;
}

// ============================================================
extern "C" void kernel_launch(void* const* d_in, const int* in_sizes, int n_in,
                              void* d_out, int out_size) {
    const float* x   = (const float*)d_in[0];
    const float* wt  = (const float*)d_in[1];
    const float* iwt = (const float*)d_in[2];
    const float* dww = (const float*)d_in[3];
    const float* dwb = (const float*)d_in[4];
    const float* pw  = (const float*)d_in[5];
    const float* pb  = (const float*)d_in[6];
    const float* ab  = (const float*)d_in[7];
    const int*   bidx= (const int*)d_in[8];
    float* out = (float*)d_out;

    (void)in_sizes; (void)n_in; (void)out_size;

    cudaFuncSetAttribute(k_proj, cudaFuncAttributeMaxDynamicSharedMemorySize, PROJ_SMEM);

    k_fwt    <<<(NWIN * DIM * 32) / 256, 256>>>(x, wt);
    k_attnmat<<<NWIN * HEADS, 256>>>(dww, dwb, ab, bidx);
    k_vrec   <<<NWIN, 256>>>();
    k_proj   <<<NWIN * 2, 256, PROJ_SMEM>>>(pw, pb);
    k_iwt    <<<(NB * DIM * RES * RES) / 256, 256>>>(iwt, out);
}